// round 5
// baseline (speedup 1.0000x reference)
#include <cuda_runtime.h>

#define NPTS    4096
#define BATCH   16
#define THREADS 256
#define QT      8
#define QPB     (THREADS * QT)   // 2048 queries per block
#define QSLICES (NPTS / QPB)     // 2
#define DS      16               // data splits
#define CH      (NPTS / DS)      // 256 data points per chunk
#define NQTOT   (2 * BATCH * NPTS)

// Per-(dir,b,query) running min of d^2, ORDER-REVERSED uint keys + atomicMax.
// Key 0 (= BSS zero-init) loses to everything -> no init kernel; sum kernel
// resets to 0 after reading (stream-ordered, graph-replay safe).
__device__ unsigned int g_minbits[NQTOT];

__device__ __forceinline__ unsigned long long pack2(float lo, float hi) {
    unsigned long long r;
    asm("mov.b64 %0, {%1, %2};" : "=l"(r) : "f"(lo), "f"(hi));
    return r;
}

// Fused: 4x fma.rn.f32x2 over two packed point-pairs, unpack + min-tree fold
// into mn — all in ONE asm scope so the movs are SSA copies ptxas eliminates.
// Final two mins form the FMNMX3 pattern min(mn, min(r0, r1)).
__device__ __forceinline__ void step4(unsigned long long qx, unsigned long long qy,
                                      unsigned long long xx0, unsigned long long yy0,
                                      unsigned long long nn0,
                                      unsigned long long xx1, unsigned long long yy1,
                                      unsigned long long nn1,
                                      float& mn) {
    asm("{\n\t"
        ".reg .b64 v0, v1;\n\t"
        ".reg .f32 a, b, c, d, r0, r1, t;\n\t"
        "fma.rn.f32x2 v0, %1, %3, %5;\n\t"
        "fma.rn.f32x2 v0, %2, %4, v0;\n\t"
        "fma.rn.f32x2 v1, %1, %6, %8;\n\t"
        "fma.rn.f32x2 v1, %2, %7, v1;\n\t"
        "mov.b64 {a, b}, v0;\n\t"
        "mov.b64 {c, d}, v1;\n\t"
        "min.f32 r0, a, b;\n\t"
        "min.f32 r1, c, d;\n\t"
        "min.f32 t, r0, r1;\n\t"
        "min.f32 %0, %0, t;\n\t"
        "}"
        : "+f"(mn)
        : "l"(qx), "l"(qy), "l"(xx0), "l"(yy0), "l"(nn0),
          "l"(xx1), "l"(yy1), "l"(nn1));
}

// order-REVERSED encoding: smaller float -> larger key; key 0 = identity.
__device__ __forceinline__ unsigned int enc_min(float f) {
    unsigned int u = __float_as_uint(f);
    unsigned int e = u ^ ((unsigned int)((int)u >> 31) | 0x80000000u);
    return ~e;
}
__device__ __forceinline__ float dec_min(unsigned int key) {
    unsigned int e = ~key;
    return (e & 0x80000000u) ? __uint_as_float(e ^ 0x80000000u)
                             : __uint_as_float(~e);
}

// One block: (query-slice, batch, dir, data-chunk).
__global__ __launch_bounds__(THREADS, 3) void chamfer_min_kernel(
    const float* __restrict__ pred,
    const float* __restrict__ target,
    float* __restrict__ out)
{
    // per group of 4 data points: [x2_01,x2_23][y2_01,y2_23][n_01,n_23]
    __shared__ ulonglong2 s_data[(CH / 4) * 3];   // 3 KB

    const int z   = blockIdx.z;
    const int dir = z & 1;
    const int ds  = z >> 1;
    const int b   = blockIdx.y;
    const int qs  = blockIdx.x;
    const int t   = threadIdx.x;

    if (z == 0 && b == 0 && qs == 0 && t < 2) out[t] = 0.0f;  // before sum kernel

    const float* qbase = (dir == 0 ? pred : target) + (size_t)b * NPTS * 2;
    const float* dbase = (dir == 0 ? target : pred) + (size_t)b * NPTS * 2;

    // fill this chunk (CH == THREADS: one point per thread)
    {
        float* sf = (float*)s_data;
        const float2* dchunk = (const float2*)dbase + ds * CH;
        float2 p = dchunk[t];
        int base = (t >> 2) * 12 + (t & 3);
        sf[base]     = -2.0f * p.x;
        sf[base + 4] = -2.0f * p.y;
        sf[base + 8] = p.x * p.x + p.y * p.y;
    }
    __syncthreads();

    // this thread's QT query points
    unsigned long long qxx[QT], qyy[QT];
    float pn[QT], mn[QT];
#pragma unroll
    for (int q = 0; q < QT; q++) {
        int qi = qs * QPB + q * THREADS + t;
        float2 p = ((const float2*)qbase)[qi];
        qxx[q] = pack2(p.x, p.x);
        qyy[q] = pack2(p.y, p.y);
        pn[q]  = p.x * p.x + p.y * p.y;
        mn[q]  = 3.4e38f;
    }

#pragma unroll 2
    for (int g = 0; g < CH / 4; g++) {
        ulonglong2 xx = s_data[g * 3 + 0];
        ulonglong2 yy = s_data[g * 3 + 1];
        ulonglong2 nn = s_data[g * 3 + 2];
#pragma unroll
        for (int q = 0; q < QT; q++)
            step4(qxx[q], qyy[q], xx.x, yy.x, nn.x, xx.y, yy.y, nn.y, mn[q]);
    }

    // fold |q|^2 in now (monotone shift), then cross-chunk combine
    const int qoff = (dir * BATCH + b) * NPTS + qs * QPB;
#pragma unroll
    for (int q = 0; q < QT; q++)
        atomicMax(&g_minbits[qoff + q * THREADS + t], enc_min(mn[q] + pn[q]));
}

// Final: decode, sum-reduce per direction, reset scratch. No input reads.
__global__ __launch_bounds__(256) void chamfer_sum_kernel(float* __restrict__ out)
{
    const int i4  = blockIdx.x * blockDim.x + threadIdx.x;   // uint4 index
    const int dir = (i4 * 4) / (BATCH * NPTS);               // uniform per block

    uint4* gp = (uint4*)g_minbits;
    uint4 k = gp[i4];
    gp[i4] = make_uint4(0u, 0u, 0u, 0u);                     // reset for replay

    float val = dec_min(k.x) + dec_min(k.y) + dec_min(k.z) + dec_min(k.w);

#pragma unroll
    for (int off = 16; off; off >>= 1)
        val += __shfl_xor_sync(0xffffffffu, val, off);

    __shared__ float s_part[8];
    int wid = threadIdx.x >> 5;
    if ((threadIdx.x & 31) == 0) s_part[wid] = val;
    __syncthreads();
    if (threadIdx.x == 0) {
        float acc = 0.0f;
#pragma unroll
        for (int w = 0; w < 8; w++) acc += s_part[w];
        atomicAdd(&out[dir], acc * (1.0f / (float)(NPTS * BATCH)));
    }
}

extern "C" void kernel_launch(void* const* d_in, const int* in_sizes, int n_in,
                              void* d_out, int out_size) {
    const float* pred   = (const float*)d_in[0];
    const float* target = (const float*)d_in[1];
    float* out = (float*)d_out;

    dim3 grid(QSLICES, BATCH, 2 * DS);
    chamfer_min_kernel<<<grid, THREADS>>>(pred, target, out);

    chamfer_sum_kernel<<<(NQTOT / 4) / 256, 256>>>(out);
}